// round 5
// baseline (speedup 1.0000x reference)
#include <cuda_runtime.h>
#include <cstdint>

#ifndef PRNG_PARTITIONABLE
#define PRNG_PARTITIONABLE 1
#endif

using u32 = unsigned int;
using u64 = unsigned long long;

#define N_ 8
#define C_ 19
#define P_ 16384
#define S_ 49152
#define IMP_ 12288
#define RND_ 4096
#define ROWS_ 131072
#define STOT_ 393216
#define SORTN_ 65536
#define XS_ 284
#define OUT_COARSE_ 622592
#define OUT_LOGITS_OFF_ 622592
#define OUT_COORDS_OFF_ 3112960

// NO device-global scratch: sort keys (4MiB) live inside the logits region of
// d_out (dead until the final fused kernel writes logits); coords go straight
// to their output slot; candidate uniforms are recomputed from threefry.

// ---------------- threefry2x32 (bit-exact vs JAX) ----------------
__device__ __forceinline__ u32 rotl32(u32 x, int r) { return (x << r) | (x >> (32 - r)); }
__device__ __forceinline__ void tf2x32(u32 k0, u32 k1, u32 x0, u32 x1, u32& o0, u32& o1) {
    u32 k2 = k0 ^ k1 ^ 0x1BD11BDAu;
    x0 += k0; x1 += k1;
#define TFR(r) { x0 += x1; x1 = rotl32(x1, r); x1 ^= x0; }
    TFR(13) TFR(15) TFR(26) TFR(6)   x0 += k1; x1 += k2 + 1u;
    TFR(17) TFR(29) TFR(16) TFR(24)  x0 += k2; x1 += k0 + 2u;
    TFR(13) TFR(15) TFR(26) TFR(6)   x0 += k0; x1 += k1 + 3u;
    TFR(17) TFR(29) TFR(16) TFR(24)  x0 += k1; x1 += k2 + 4u;
    TFR(13) TFR(15) TFR(26) TFR(6)   x0 += k2; x1 += k0 + 5u;
#undef TFR
    o0 = x0; o1 = x1;
}
__device__ __forceinline__ float bits_to_uniform(u32 b) {
    float f = __uint_as_float(0x3f800000u | (b >> 9));
    f = __fsub_rn(f, 1.0f);
    return fmaxf(0.0f, f);
}
// split(key(7)) -> k1 (candidates), k2 (random tail)
__device__ __forceinline__ void derive_keys(u32& k1a, u32& k1b, u32& k2a, u32& k2b) {
#if PRNG_PARTITIONABLE
    tf2x32(0u, 7u, 0u, 0u, k1a, k1b);
    tf2x32(0u, 7u, 0u, 1u, k2a, k2b);
#else
    u32 A0, A1, B0, B1;
    tf2x32(0u, 7u, 0u, 2u, A0, A1);
    tf2x32(0u, 7u, 1u, 3u, B0, B1);
    k1a = A0; k1b = B0; k2a = A1; k2b = B1;
#endif
}
__device__ __forceinline__ float cand_uniform(u32 ka, u32 kb, u32 i) {
#if PRNG_PARTITIONABLE
    u32 a, b; tf2x32(ka, kb, 0u, i, a, b);
    return bits_to_uniform(a ^ b);
#else
    const u32 h = 393216u;
    u32 p = (i < h) ? i : i - h;
    u32 a, b; tf2x32(ka, kb, p, p + h, a, b);
    return bits_to_uniform((i < h) ? a : b);
#endif
}
__device__ __forceinline__ float rand_uniform(u32 ka, u32 kb, u32 i) {
#if PRNG_PARTITIONABLE
    u32 a, b; tf2x32(ka, kb, 0u, i, a, b);
    return bits_to_uniform(a ^ b);
#else
    const u32 h = 32768u;
    u32 p = (i < h) ? i : i - h;
    u32 a, b; tf2x32(ka, kb, p, p + h, a, b);
    return bits_to_uniform((i < h) ? a : b);
#endif
}

// ---------------- random-tail coords ----------------
__global__ void k_gen_random(float* __restrict__ out_coords) {
    int i = blockIdx.x * blockDim.x + threadIdx.x;
    if (i >= N_ * RND_ * 2) return;
    u32 k1a, k1b, k2a, k2b;
    derive_keys(k1a, k1b, k2a, k2b);
    float u = rand_uniform(k2a, k2b, (u32)i);
    int n = i >> 13;
    int rem = i & 8191;
    out_coords[(size_t)((n << 14) + IMP_ + (rem >> 1)) * 2 + (rem & 1)] = u;
}

// ---------------- uncertainty + sort keys (exact fp order, no FMA) ---------
__global__ void k_unc_keys(const float* __restrict__ coarse, u64* __restrict__ keys) {
    int t = blockIdx.x * blockDim.x + threadIdx.x;
    if (t >= N_ * SORTN_) return;
    int n = t >> 16;
    int s = t & (SORTN_ - 1);
    if (s >= S_) { keys[t] = ~0ull; return; }
    u32 k1a, k1b, k2a, k2b;
    derive_keys(k1a, k1b, k2a, k2b);
    u32 i0 = ((u32)n * S_ + (u32)s) * 2u;
    float cx = cand_uniform(k1a, k1b, i0);
    float cy = cand_uniform(k1a, k1b, i0 + 1u);
    float x = __fsub_rn(__fmul_rn(cx, 64.0f), 0.5f);
    float y = __fsub_rn(__fmul_rn(cy, 64.0f), 0.5f);
    float x0 = floorf(x), y0 = floorf(y);
    float x1 = __fadd_rn(x0, 1.0f), y1 = __fadd_rn(y0, 1.0f);
    float wx1 = __fsub_rn(x, x0), wy1 = __fsub_rn(y, y0);
    float wx0 = __fsub_rn(1.0f, wx1), wy0 = __fsub_rn(1.0f, wy1);
    float m00 = (x0 >= 0.f && x0 <= 63.f && y0 >= 0.f && y0 <= 63.f) ? 1.f : 0.f;
    float m01 = (x1 >= 0.f && x1 <= 63.f && y0 >= 0.f && y0 <= 63.f) ? 1.f : 0.f;
    float m10 = (x0 >= 0.f && x0 <= 63.f && y1 >= 0.f && y1 <= 63.f) ? 1.f : 0.f;
    float m11 = (x1 >= 0.f && x1 <= 63.f && y1 >= 0.f && y1 <= 63.f) ? 1.f : 0.f;
    int ix0 = (int)fminf(fmaxf(x0, 0.f), 63.f);
    int ix1 = (int)fminf(fmaxf(x1, 0.f), 63.f);
    int iy0 = (int)fminf(fmaxf(y0, 0.f), 63.f);
    int iy1 = (int)fminf(fmaxf(y1, 0.f), 63.f);
    float w00 = __fmul_rn(wy0, wx0), w01 = __fmul_rn(wy0, wx1);
    float w10 = __fmul_rn(wy1, wx0), w11 = __fmul_rn(wy1, wx1);
    const float* base = coarse + (size_t)n * C_ * 4096;
    int i00 = iy0 * 64 + ix0, i01 = iy0 * 64 + ix1;
    int i10 = iy1 * 64 + ix0, i11 = iy1 * 64 + ix1;
    float mx1 = -3.402823466e38f, mx2 = -3.402823466e38f;
#pragma unroll
    for (int c = 0; c < C_; c++) {
        const float* ch = base + c * 4096;
        float a = __fmul_rn(__fmul_rn(__ldg(ch + i00), m00), w00);
        float b = __fmul_rn(__fmul_rn(__ldg(ch + i01), m01), w01);
        float d = __fmul_rn(__fmul_rn(__ldg(ch + i10), m10), w10);
        float e = __fmul_rn(__fmul_rn(__ldg(ch + i11), m11), w11);
        float v = __fadd_rn(__fadd_rn(__fadd_rn(a, b), d), e);
        if (v > mx1) { mx2 = mx1; mx1 = v; }
        else if (v > mx2) { mx2 = v; }
    }
    float unc = __fsub_rn(mx2, mx1);
    u32 ub = __float_as_uint(unc);
    if ((ub << 1) == 0u) ub = 0u;
    u32 asc = (ub & 0x80000000u) ? ~ub : (ub | 0x80000000u);
    keys[t] = ((u64)(~asc) << 32) | (u64)(u32)s;
}

// ---------------- bitonic sort: 8 rows x 65536 u64 ----------------
__global__ void k_bitonic_global(u64* __restrict__ keys, int k, int j) {
    int t = blockIdx.x * blockDim.x + threadIdx.x;
    int row = t >> 16;
    int i = t & (SORTN_ - 1);
    int l = i ^ j;
    if (l > i) {
        u64* a = keys + ((size_t)row << 16);
        u64 x = a[i], y = a[l];
        bool up = ((i & k) == 0);
        if (up ? (x > y) : (x < y)) { a[i] = y; a[l] = x; }
    }
}
__global__ void k_bitonic_local(u64* __restrict__ keys, int kbig) {
    __shared__ u64 sh[2048];
    int row = blockIdx.x >> 5;
    int tile = blockIdx.x & 31;
    u64* g = keys + ((size_t)row << 16) + (tile << 11);
    int t = threadIdx.x;
    sh[t] = g[t]; sh[t + 1024] = g[t + 1024];
    __syncthreads();
    int gbase = tile << 11;
    if (kbig == 0) {
        for (int k = 2; k <= 2048; k <<= 1)
            for (int j = k >> 1; j > 0; j >>= 1) {
                int i = ((t & ~(j - 1)) << 1) | (t & (j - 1));
                int l = i | j;
                bool up = (((gbase + i) & k) == 0);
                u64 x = sh[i], y = sh[l];
                if (up ? (x > y) : (x < y)) { sh[i] = y; sh[l] = x; }
                __syncthreads();
            }
    } else {
        for (int j = 1024; j > 0; j >>= 1) {
            int i = ((t & ~(j - 1)) << 1) | (t & (j - 1));
            int l = i | j;
            bool up = (((gbase + i) & kbig) == 0);
            u64 x = sh[i], y = sh[l];
            if (up ? (x > y) : (x < y)) { sh[i] = y; sh[l] = x; }
            __syncthreads();
        }
    }
    g[t] = sh[t]; g[t + 1024] = sh[t + 1024];
}

// ---------------- gather importance coords (recompute PRNG) -----------------
__global__ void k_gather_imp(const u64* __restrict__ keys, float* __restrict__ out_coords) {
    int t = blockIdx.x * blockDim.x + threadIdx.x;
    if (t >= N_ * IMP_) return;
    int n = t / IMP_;
    int p = t - n * IMP_;
    u64 key = keys[((size_t)n << 16) + p];
    u32 s = (u32)key;
    u32 k1a, k1b, k2a, k2b;
    derive_keys(k1a, k1b, k2a, k2b);
    u32 i0 = ((u32)n * S_ + s) * 2u;
    float cx = cand_uniform(k1a, k1b, i0);
    float cy = cand_uniform(k1a, k1b, i0 + 1u);
    size_t o = ((size_t)n * P_ + p) * 2;
    out_coords[o] = cx; out_coords[o + 1] = cy;
}

// ---------------- fused sampling + MLP + head -------------------------------
// Block: 64 points, 256 threads. smem: xbuf[64][284] + wbuf[5320].
__global__ void __launch_bounds__(256) k_mlp(
    const float* __restrict__ coarse, const float* __restrict__ features,
    const float* __restrict__ w0, const float* __restrict__ b0,
    const float* __restrict__ w1, const float* __restrict__ b1,
    const float* __restrict__ w2, const float* __restrict__ b2,
    const float* __restrict__ wp, const float* __restrict__ bp,
    const float* __restrict__ coords, float* __restrict__ logits) {
    extern __shared__ float sm[];
    float* xbuf = sm;                  // 64 * 284
    float* wbuf = sm + 64 * XS_;       // 5320
    int tid = threadIdx.x;
    int pt0g = blockIdx.x * 64;
    int nimg = pt0g >> 14;             // block never straddles images (64 | 16384)

    // ---- fine sampling: 4 threads per point, 64 channels each ----
    {
        int tpt = tid >> 2;
        int q = tid & 3;
        int gp = pt0g + tpt;
        float cx = coords[(size_t)gp * 2], cy = coords[(size_t)gp * 2 + 1];
        float x = cx * 128.f - 0.5f, y = cy * 128.f - 0.5f;
        float x0f = floorf(x), y0f = floorf(y);
        float wx1 = x - x0f, wy1 = y - y0f;
        float wx0 = 1.f - wx1, wy0 = 1.f - wy1;
        float w00 = wy0 * wx0, w01 = wy0 * wx1, w10 = wy1 * wx0, w11 = wy1 * wx1;
        if (x0f < 0.f)   { w00 = 0.f; w10 = 0.f; }
        if (x0f > 126.f) { w01 = 0.f; w11 = 0.f; }
        if (y0f < 0.f)   { w00 = 0.f; w01 = 0.f; }
        if (y0f > 126.f) { w10 = 0.f; w11 = 0.f; }
        // clip x0 and x0+1 INDEPENDENTLY (x0=-1 => x1 gathers column 0)
        int ix0 = (int)fminf(fmaxf(x0f, 0.f), 127.f);
        int ix1 = (int)fminf(fmaxf(x0f + 1.f, 0.f), 127.f);
        int iy0 = (int)fminf(fmaxf(y0f, 0.f), 127.f);
        int iy1 = (int)fminf(fmaxf(y0f + 1.f, 0.f), 127.f);
        const float* f = features + (size_t)nimg * 256 * 16384;
        int i00 = iy0 * 128 + ix0, i01 = iy0 * 128 + ix1;
        int i10 = iy1 * 128 + ix0, i11 = iy1 * 128 + ix1;
        int c0 = q * 64;
#pragma unroll 4
        for (int c = c0; c < c0 + 64; ++c) {
            const float* fc = f + (size_t)c * 16384;
            float v = w00 * __ldg(fc + i00) + w01 * __ldg(fc + i01)
                    + w10 * __ldg(fc + i10) + w11 * __ldg(fc + i11);
            xbuf[tpt * XS_ + c] = v;
        }
    }
    // ---- coarse sampling + zero pad: 1 thread per point ----
    if (tid < 64) {
        int gp = pt0g + tid;
        float cx = coords[(size_t)gp * 2], cy = coords[(size_t)gp * 2 + 1];
        float x = cx * 64.f - 0.5f, y = cy * 64.f - 0.5f;
        float x0f = floorf(x), y0f = floorf(y);
        float wx1 = x - x0f, wy1 = y - y0f;
        float wx0 = 1.f - wx1, wy0 = 1.f - wy1;
        float w00 = wy0 * wx0, w01 = wy0 * wx1, w10 = wy1 * wx0, w11 = wy1 * wx1;
        if (x0f < 0.f)  { w00 = 0.f; w10 = 0.f; }
        if (x0f > 62.f) { w01 = 0.f; w11 = 0.f; }
        if (y0f < 0.f)  { w00 = 0.f; w01 = 0.f; }
        if (y0f > 62.f) { w10 = 0.f; w11 = 0.f; }
        int ix0 = (int)fminf(fmaxf(x0f, 0.f), 63.f);
        int ix1 = (int)fminf(fmaxf(x0f + 1.f, 0.f), 63.f);
        int iy0 = (int)fminf(fmaxf(y0f, 0.f), 63.f);
        int iy1 = (int)fminf(fmaxf(y0f + 1.f, 0.f), 63.f);
        const float* base = coarse + (size_t)nimg * C_ * 4096;
        int i00 = iy0 * 64 + ix0, i01 = iy0 * 64 + ix1;
        int i10 = iy1 * 64 + ix0, i11 = iy1 * 64 + ix1;
#pragma unroll
        for (int c = 0; c < C_; ++c) {
            const float* ch = base + c * 4096;
            float v = w00 * __ldg(ch + i00) + w01 * __ldg(ch + i01)
                    + w10 * __ldg(ch + i10) + w11 * __ldg(ch + i11);
            xbuf[tid * XS_ + 256 + c] = v;
        }
#pragma unroll
        for (int c = 275; c < XS_; ++c) xbuf[tid * XS_ + c] = 0.f;
    }

    // ---- 3 hidden layers: 64x256 <- 64x280 . 280x256 ----
    const float* Ws[3] = { w0, w1, w2 };
    const float* Bs[3] = { b0, b1, b2 };
    int pt0 = (tid >> 5) * 8;      // warp -> 8 points
    int o0 = (tid & 31) * 8;       // lane -> 8 outputs
#pragma unroll 1
    for (int layer = 0; layer < 3; ++layer) {
        const float* W = Ws[layer];
        float acc[8][8];
#pragma unroll
        for (int i = 0; i < 8; i++)
#pragma unroll
            for (int j = 0; j < 8; j++) acc[i][j] = 0.f;
#pragma unroll 1
        for (int k0 = 0; k0 < XS_ - 4; k0 += 8) {   // 0..272 step 8 -> 35 iters (280)
            __syncthreads();
#pragma unroll
            for (int kk = 0; kk < 8; ++kk) {
                int k = k0 + kk;
                wbuf[kk * 256 + tid] = (k < 275) ? __ldg(W + tid * 275 + k) : 0.f;
            }
            __syncthreads();
#pragma unroll
            for (int kk = 0; kk < 8; ++kk) {
                float xv[8];
#pragma unroll
                for (int i = 0; i < 8; ++i) xv[i] = xbuf[(pt0 + i) * XS_ + k0 + kk];
                float4 ba = *(const float4*)&wbuf[kk * 256 + o0];
                float4 bb = *(const float4*)&wbuf[kk * 256 + o0 + 4];
                float bv[8] = { ba.x, ba.y, ba.z, ba.w, bb.x, bb.y, bb.z, bb.w };
#pragma unroll
                for (int i = 0; i < 8; ++i)
#pragma unroll
                    for (int j = 0; j < 8; ++j) acc[i][j] += xv[i] * bv[j];
            }
        }
        __syncthreads();
        float4 ba = *(const float4*)(Bs[layer] + o0);
        float4 bb = *(const float4*)(Bs[layer] + o0 + 4);
        float bias[8] = { ba.x, ba.y, ba.z, ba.w, bb.x, bb.y, bb.z, bb.w };
#pragma unroll
        for (int i = 0; i < 8; ++i) {
            float4 r0, r1;
            r0.x = fmaxf(acc[i][0] + bias[0], 0.f);
            r0.y = fmaxf(acc[i][1] + bias[1], 0.f);
            r0.z = fmaxf(acc[i][2] + bias[2], 0.f);
            r0.w = fmaxf(acc[i][3] + bias[3], 0.f);
            r1.x = fmaxf(acc[i][4] + bias[4], 0.f);
            r1.y = fmaxf(acc[i][5] + bias[5], 0.f);
            r1.z = fmaxf(acc[i][6] + bias[6], 0.f);
            r1.w = fmaxf(acc[i][7] + bias[7], 0.f);
            *(float4*)&xbuf[(pt0 + i) * XS_ + o0] = r0;
            *(float4*)&xbuf[(pt0 + i) * XS_ + o0 + 4] = r1;
        }
        __syncthreads();
    }

    // ---- head: 19 outputs per point ----
    for (int idx = tid; idx < 19 * 280; idx += 256) {
        int c = idx / 280, k = idx - c * 280;
        wbuf[idx] = (k < 275) ? __ldg(wp + c * 275 + k) : 0.f;
    }
    __syncthreads();
    for (int oidx = tid; oidx < 64 * C_; oidx += 256) {
        int pt = oidx / C_, c = oidx - pt * C_;
        const float* xr = &xbuf[pt * XS_];
        const float* wr = &wbuf[c * 280];
        float acc = 0.f;
#pragma unroll 10
        for (int k = 0; k < 280; k += 4) {
            float4 xv = *(const float4*)&xr[k];
            float4 wv = *(const float4*)&wr[k];
            acc += xv.x * wv.x + xv.y * wv.y + xv.z * wv.z + xv.w * wv.w;
        }
        int gp = pt0g + pt;
        int n = gp >> 14, p = gp & 16383;
        logits[((size_t)(n * C_ + c) << 14) + p] = acc + __ldg(bp + c);
    }
}

// ---------------- launch ----------------
extern "C" void kernel_launch(void* const* d_in, const int* in_sizes, int n_in,
                              void* d_out, int out_size) {
    const float* coarse = (const float*)d_in[0];
    const float* features = (const float*)d_in[1];
    const float* w0 = (const float*)d_in[2];
    const float* b0 = (const float*)d_in[3];
    const float* w1 = (const float*)d_in[4];
    const float* b1 = (const float*)d_in[5];
    const float* w2 = (const float*)d_in[6];
    const float* b2 = (const float*)d_in[7];
    const float* wp = (const float*)d_in[8];
    const float* bp = (const float*)d_in[9];
    float* out = (float*)d_out;
    float* out_coords = out + OUT_COORDS_OFF_;
    float* out_logits = out + OUT_LOGITS_OFF_;
    // sort keys live in the (not-yet-written) logits region: 4MiB < 9.96MiB
    u64* keys = (u64*)(out + OUT_LOGITS_OFF_);

    const int smem_mlp = (64 * XS_ + 5320) * sizeof(float);   // 93,984 B
    cudaFuncSetAttribute(k_mlp, cudaFuncAttributeMaxDynamicSharedMemorySize, smem_mlp);

    // coarse passthrough
    cudaMemcpyAsync(out, coarse, (size_t)OUT_COARSE_ * sizeof(float),
                    cudaMemcpyDeviceToDevice, 0);

    k_gen_random<<<(N_ * RND_ * 2 + 255) / 256, 256>>>(out_coords);
    k_unc_keys<<<(N_ * SORTN_) / 256, 256>>>(coarse, keys);

    k_bitonic_local<<<256, 1024>>>(keys, 0);
    for (int k = 4096; k <= 65536; k <<= 1) {
        for (int j = k >> 1; j >= 2048; j >>= 1)
            k_bitonic_global<<<(N_ * SORTN_) / 256, 256>>>(keys, k, j);
        k_bitonic_local<<<256, 1024>>>(keys, k);
    }

    k_gather_imp<<<(N_ * IMP_ + 255) / 256, 256>>>(keys, out_coords);

    // fused sampling + MLP + head (overwrites the keys scratch with logits)
    k_mlp<<<ROWS_ / 64, 256, smem_mlp>>>(coarse, features, w0, b0, w1, b1,
                                         w2, b2, wp, bp, out_coords, out_logits);
}

// round 7
// speedup vs baseline: 1.6321x; 1.6321x over previous
#include <cuda_runtime.h>
#include <cuda_bf16.h>
#include <cstdint>

#ifndef PRNG_PARTITIONABLE
#define PRNG_PARTITIONABLE 1
#endif

using u32 = unsigned int;
using u64 = unsigned long long;

#define N_ 8
#define C_ 19
#define P_ 16384
#define S_ 49152
#define IMP_ 12288
#define RND_ 4096
#define ROWS_ 131072
#define SORTN_ 65536
#define OUT_COARSE_ 622592
#define OUT_LOGITS_OFF_ 622592
#define OUT_COORDS_OFF_ 3112960

// ---- fused-kernel smem layout (plain padded tiles, no swizzle) ----
// X: 128 rows x 296 cols bf16 (stride 592B = 37*16B, 37%8=5 -> ldmatrix conflict-free)
// W: 256 rows x 40 cols bf16 (stride 80B = 5*16B, conflict-free), 32 k per chunk
#define XSTR 592
#define WSTR 80
#define SM_XHI 0
#define SM_XLO 75776
#define SM_WHI 151552
#define SM_WLO 172032
#define SMEM_TOTAL 192512

// ---------------- threefry2x32 (bit-exact vs JAX) ----------------
__device__ __forceinline__ u32 rotl32(u32 x, int r) { return (x << r) | (x >> (32 - r)); }
__device__ __forceinline__ void tf2x32(u32 k0, u32 k1, u32 x0, u32 x1, u32& o0, u32& o1) {
    u32 k2 = k0 ^ k1 ^ 0x1BD11BDAu;
    x0 += k0; x1 += k1;
#define TFR(r) { x0 += x1; x1 = rotl32(x1, r); x1 ^= x0; }
    TFR(13) TFR(15) TFR(26) TFR(6)   x0 += k1; x1 += k2 + 1u;
    TFR(17) TFR(29) TFR(16) TFR(24)  x0 += k2; x1 += k0 + 2u;
    TFR(13) TFR(15) TFR(26) TFR(6)   x0 += k0; x1 += k1 + 3u;
    TFR(17) TFR(29) TFR(16) TFR(24)  x0 += k1; x1 += k2 + 4u;
    TFR(13) TFR(15) TFR(26) TFR(6)   x0 += k2; x1 += k0 + 5u;
#undef TFR
    o0 = x0; o1 = x1;
}
__device__ __forceinline__ float bits_to_uniform(u32 b) {
    float f = __uint_as_float(0x3f800000u | (b >> 9));
    f = __fsub_rn(f, 1.0f);
    return fmaxf(0.0f, f);
}
__device__ __forceinline__ void derive_keys(u32& k1a, u32& k1b, u32& k2a, u32& k2b) {
#if PRNG_PARTITIONABLE
    tf2x32(0u, 7u, 0u, 0u, k1a, k1b);
    tf2x32(0u, 7u, 0u, 1u, k2a, k2b);
#else
    u32 A0, A1, B0, B1;
    tf2x32(0u, 7u, 0u, 2u, A0, A1);
    tf2x32(0u, 7u, 1u, 3u, B0, B1);
    k1a = A0; k1b = B0; k2a = A1; k2b = B1;
#endif
}
__device__ __forceinline__ float cand_uniform(u32 ka, u32 kb, u32 i) {
#if PRNG_PARTITIONABLE
    u32 a, b; tf2x32(ka, kb, 0u, i, a, b);
    return bits_to_uniform(a ^ b);
#else
    const u32 h = 393216u;
    u32 p = (i < h) ? i : i - h;
    u32 a, b; tf2x32(ka, kb, p, p + h, a, b);
    return bits_to_uniform((i < h) ? a : b);
#endif
}
__device__ __forceinline__ float rand_uniform(u32 ka, u32 kb, u32 i) {
#if PRNG_PARTITIONABLE
    u32 a, b; tf2x32(ka, kb, 0u, i, a, b);
    return bits_to_uniform(a ^ b);
#else
    const u32 h = 32768u;
    u32 p = (i < h) ? i : i - h;
    u32 a, b; tf2x32(ka, kb, p, p + h, a, b);
    return bits_to_uniform((i < h) ? a : b);
#endif
}

// ---------------- selection pipeline (unchanged; passing since R5) ----------
__global__ void k_gen_random(float* __restrict__ out_coords) {
    int i = blockIdx.x * blockDim.x + threadIdx.x;
    if (i >= N_ * RND_ * 2) return;
    u32 k1a, k1b, k2a, k2b;
    derive_keys(k1a, k1b, k2a, k2b);
    float u = rand_uniform(k2a, k2b, (u32)i);
    int n = i >> 13;
    int rem = i & 8191;
    out_coords[(size_t)((n << 14) + IMP_ + (rem >> 1)) * 2 + (rem & 1)] = u;
}

__global__ void k_unc_keys(const float* __restrict__ coarse, u64* __restrict__ keys) {
    int t = blockIdx.x * blockDim.x + threadIdx.x;
    if (t >= N_ * SORTN_) return;
    int n = t >> 16;
    int s = t & (SORTN_ - 1);
    if (s >= S_) { keys[t] = ~0ull; return; }
    u32 k1a, k1b, k2a, k2b;
    derive_keys(k1a, k1b, k2a, k2b);
    u32 i0 = ((u32)n * S_ + (u32)s) * 2u;
    float cx = cand_uniform(k1a, k1b, i0);
    float cy = cand_uniform(k1a, k1b, i0 + 1u);
    float x = __fsub_rn(__fmul_rn(cx, 64.0f), 0.5f);
    float y = __fsub_rn(__fmul_rn(cy, 64.0f), 0.5f);
    float x0 = floorf(x), y0 = floorf(y);
    float x1 = __fadd_rn(x0, 1.0f), y1 = __fadd_rn(y0, 1.0f);
    float wx1 = __fsub_rn(x, x0), wy1 = __fsub_rn(y, y0);
    float wx0 = __fsub_rn(1.0f, wx1), wy0 = __fsub_rn(1.0f, wy1);
    float m00 = (x0 >= 0.f && x0 <= 63.f && y0 >= 0.f && y0 <= 63.f) ? 1.f : 0.f;
    float m01 = (x1 >= 0.f && x1 <= 63.f && y0 >= 0.f && y0 <= 63.f) ? 1.f : 0.f;
    float m10 = (x0 >= 0.f && x0 <= 63.f && y1 >= 0.f && y1 <= 63.f) ? 1.f : 0.f;
    float m11 = (x1 >= 0.f && x1 <= 63.f && y1 >= 0.f && y1 <= 63.f) ? 1.f : 0.f;
    int ix0 = (int)fminf(fmaxf(x0, 0.f), 63.f);
    int ix1 = (int)fminf(fmaxf(x1, 0.f), 63.f);
    int iy0 = (int)fminf(fmaxf(y0, 0.f), 63.f);
    int iy1 = (int)fminf(fmaxf(y1, 0.f), 63.f);
    float w00 = __fmul_rn(wy0, wx0), w01 = __fmul_rn(wy0, wx1);
    float w10 = __fmul_rn(wy1, wx0), w11 = __fmul_rn(wy1, wx1);
    const float* base = coarse + (size_t)n * C_ * 4096;
    int i00 = iy0 * 64 + ix0, i01 = iy0 * 64 + ix1;
    int i10 = iy1 * 64 + ix0, i11 = iy1 * 64 + ix1;
    float mx1 = -3.402823466e38f, mx2 = -3.402823466e38f;
#pragma unroll
    for (int c = 0; c < C_; c++) {
        const float* ch = base + c * 4096;
        float a = __fmul_rn(__fmul_rn(__ldg(ch + i00), m00), w00);
        float b = __fmul_rn(__fmul_rn(__ldg(ch + i01), m01), w01);
        float d = __fmul_rn(__fmul_rn(__ldg(ch + i10), m10), w10);
        float e = __fmul_rn(__fmul_rn(__ldg(ch + i11), m11), w11);
        float v = __fadd_rn(__fadd_rn(__fadd_rn(a, b), d), e);
        if (v > mx1) { mx2 = mx1; mx1 = v; }
        else if (v > mx2) { mx2 = v; }
    }
    float unc = __fsub_rn(mx2, mx1);
    u32 ub = __float_as_uint(unc);
    if ((ub << 1) == 0u) ub = 0u;
    u32 asc = (ub & 0x80000000u) ? ~ub : (ub | 0x80000000u);
    keys[t] = ((u64)(~asc) << 32) | (u64)(u32)s;
}

__global__ void k_bitonic_global(u64* __restrict__ keys, int k, int j) {
    int t = blockIdx.x * blockDim.x + threadIdx.x;
    int row = t >> 16;
    int i = t & (SORTN_ - 1);
    int l = i ^ j;
    if (l > i) {
        u64* a = keys + ((size_t)row << 16);
        u64 x = a[i], y = a[l];
        bool up = ((i & k) == 0);
        if (up ? (x > y) : (x < y)) { a[i] = y; a[l] = x; }
    }
}
__global__ void k_bitonic_local(u64* __restrict__ keys, int kbig) {
    __shared__ u64 sh[2048];
    int row = blockIdx.x >> 5;
    int tile = blockIdx.x & 31;
    u64* g = keys + ((size_t)row << 16) + (tile << 11);
    int t = threadIdx.x;
    sh[t] = g[t]; sh[t + 1024] = g[t + 1024];
    __syncthreads();
    int gbase = tile << 11;
    if (kbig == 0) {
        for (int k = 2; k <= 2048; k <<= 1)
            for (int j = k >> 1; j > 0; j >>= 1) {
                int i = ((t & ~(j - 1)) << 1) | (t & (j - 1));
                int l = i | j;
                bool up = (((gbase + i) & k) == 0);
                u64 x = sh[i], y = sh[l];
                if (up ? (x > y) : (x < y)) { sh[i] = y; sh[l] = x; }
                __syncthreads();
            }
    } else {
        for (int j = 1024; j > 0; j >>= 1) {
            int i = ((t & ~(j - 1)) << 1) | (t & (j - 1));
            int l = i | j;
            bool up = (((gbase + i) & kbig) == 0);
            u64 x = sh[i], y = sh[l];
            if (up ? (x > y) : (x < y)) { sh[i] = y; sh[l] = x; }
            __syncthreads();
        }
    }
    g[t] = sh[t]; g[t + 1024] = sh[t + 1024];
}

__global__ void k_gather_imp(const u64* __restrict__ keys, float* __restrict__ out_coords) {
    int t = blockIdx.x * blockDim.x + threadIdx.x;
    if (t >= N_ * IMP_) return;
    int n = t / IMP_;
    int p = t - n * IMP_;
    u64 key = keys[((size_t)n << 16) + p];
    u32 s = (u32)key;
    u32 k1a, k1b, k2a, k2b;
    derive_keys(k1a, k1b, k2a, k2b);
    u32 i0 = ((u32)n * S_ + s) * 2u;
    float cx = cand_uniform(k1a, k1b, i0);
    float cy = cand_uniform(k1a, k1b, i0 + 1u);
    size_t o = ((size_t)n * P_ + p) * 2;
    out_coords[o] = cx; out_coords[o + 1] = cy;
}

// ---------------- mma.sync helpers ----------------
__device__ __forceinline__ u32 smem_u32(const void* p) {
    u32 a;
    asm("{ .reg .u64 t; cvta.to.shared.u64 t, %1; cvt.u32.u64 %0, t; }" : "=r"(a) : "l"(p));
    return a;
}
__device__ __forceinline__ void ldsm_x4(u32& r0, u32& r1, u32& r2, u32& r3, u32 addr) {
    asm volatile("ldmatrix.sync.aligned.m8n8.x4.shared.b16 {%0,%1,%2,%3}, [%4];"
                 : "=r"(r0), "=r"(r1), "=r"(r2), "=r"(r3) : "r"(addr));
}
__device__ __forceinline__ void mma_bf16(float* d, u32 a0, u32 a1, u32 a2, u32 a3,
                                         u32 b0, u32 b1) {
    asm volatile("mma.sync.aligned.m16n8k16.row.col.f32.bf16.bf16.f32 "
                 "{%0,%1,%2,%3}, {%4,%5,%6,%7}, {%8,%9}, {%0,%1,%2,%3};"
                 : "+f"(d[0]), "+f"(d[1]), "+f"(d[2]), "+f"(d[3])
                 : "r"(a0), "r"(a1), "r"(a2), "r"(a3), "r"(b0), "r"(b1));
}
__device__ __forceinline__ void sts16(u32 addr, __nv_bfloat16 v) {
    unsigned short raw = *reinterpret_cast<unsigned short*>(&v);
    asm volatile("st.shared.b16 [%0], %1;" :: "r"(addr), "h"(raw));
}
// fp32 -> bf16 hi/lo split into X tiles (row stride XSTR bytes)
__device__ __forceinline__ void xsplit(u32 sbase, int row, int col, float v) {
    u32 off = (u32)(row * XSTR + col * 2);
    __nv_bfloat16 h = __float2bfloat16(v);
    float r = v - __bfloat162float(h);
    sts16(sbase + SM_XHI + off, h);
    sts16(sbase + SM_XLO + off, __float2bfloat16(r));
}
__device__ __forceinline__ void wsplit(u32 sbase, int row, int col, float v) {
    u32 off = (u32)(row * WSTR + col * 2);
    __nv_bfloat16 h = __float2bfloat16(v);
    float r = v - __bfloat162float(h);
    sts16(sbase + SM_WHI + off, h);
    sts16(sbase + SM_WLO + off, __float2bfloat16(r));
}

// ---------------- fused sampling + 3-layer MLP + head (mma.sync bf16x3) -----
__global__ void __launch_bounds__(512) k_fused(
    const float* __restrict__ coarse, const float* __restrict__ features,
    const float* __restrict__ w0, const float* __restrict__ b0,
    const float* __restrict__ w1, const float* __restrict__ b1,
    const float* __restrict__ w2, const float* __restrict__ b2,
    const float* __restrict__ wp, const float* __restrict__ bp,
    const float* __restrict__ coords, float* __restrict__ logits) {
    extern __shared__ char smem[];
    u32 sbase = smem_u32(smem);
    int tid = threadIdx.x, lane = tid & 31, warp = tid >> 5;
    int mt = warp >> 1, half = warp & 1;
    int r0 = mt * 16;
    int pt0g = blockIdx.x * 128;
    int nimg = pt0g >> 14;

    // ---- fine sampling: 4 threads/point, 64 channels each ----
    {
        int tpt = tid >> 2, q = tid & 3;
        int gp = pt0g + tpt;
        float cx = coords[(size_t)gp * 2], cy = coords[(size_t)gp * 2 + 1];
        float x = cx * 128.f - 0.5f, y = cy * 128.f - 0.5f;
        float x0f = floorf(x), y0f = floorf(y);
        float wx1 = x - x0f, wy1 = y - y0f;
        float wx0 = 1.f - wx1, wy0 = 1.f - wy1;
        float w00 = wy0 * wx0, w01 = wy0 * wx1, w10 = wy1 * wx0, w11 = wy1 * wx1;
        if (x0f < 0.f)   { w00 = 0.f; w10 = 0.f; }
        if (x0f > 126.f) { w01 = 0.f; w11 = 0.f; }
        if (y0f < 0.f)   { w00 = 0.f; w01 = 0.f; }
        if (y0f > 126.f) { w10 = 0.f; w11 = 0.f; }
        int ix0 = (int)fminf(fmaxf(x0f, 0.f), 127.f);
        int ix1 = (int)fminf(fmaxf(x0f + 1.f, 0.f), 127.f);
        int iy0 = (int)fminf(fmaxf(y0f, 0.f), 127.f);
        int iy1 = (int)fminf(fmaxf(y0f + 1.f, 0.f), 127.f);
        const float* f = features + (size_t)nimg * 256 * 16384;
        int i00 = iy0 * 128 + ix0, i01 = iy0 * 128 + ix1;
        int i10 = iy1 * 128 + ix0, i11 = iy1 * 128 + ix1;
        int c0 = q * 64;
#pragma unroll 4
        for (int c = c0; c < c0 + 64; ++c) {
            const float* fc = f + (size_t)c * 16384;
            float v = w00 * __ldg(fc + i00) + w01 * __ldg(fc + i01)
                    + w10 * __ldg(fc + i10) + w11 * __ldg(fc + i11);
            xsplit(sbase, tpt, c, v);
        }
    }
    // ---- coarse sampling -> cols 256..274 ----
    if (tid < 128) {
        int gp = pt0g + tid;
        float cx = coords[(size_t)gp * 2], cy = coords[(size_t)gp * 2 + 1];
        float x = cx * 64.f - 0.5f, y = cy * 64.f - 0.5f;
        float x0f = floorf(x), y0f = floorf(y);
        float wx1 = x - x0f, wy1 = y - y0f;
        float wx0 = 1.f - wx1, wy0 = 1.f - wy1;
        float w00 = wy0 * wx0, w01 = wy0 * wx1, w10 = wy1 * wx0, w11 = wy1 * wx1;
        if (x0f < 0.f)  { w00 = 0.f; w10 = 0.f; }
        if (x0f > 62.f) { w01 = 0.f; w11 = 0.f; }
        if (y0f < 0.f)  { w00 = 0.f; w01 = 0.f; }
        if (y0f > 62.f) { w10 = 0.f; w11 = 0.f; }
        int ix0 = (int)fminf(fmaxf(x0f, 0.f), 63.f);
        int ix1 = (int)fminf(fmaxf(x0f + 1.f, 0.f), 63.f);
        int iy0 = (int)fminf(fmaxf(y0f, 0.f), 63.f);
        int iy1 = (int)fminf(fmaxf(y0f + 1.f, 0.f), 63.f);
        const float* base = coarse + (size_t)nimg * C_ * 4096;
        int i00 = iy0 * 64 + ix0, i01 = iy0 * 64 + ix1;
        int i10 = iy1 * 64 + ix0, i11 = iy1 * 64 + ix1;
#pragma unroll
        for (int c = 0; c < C_; ++c) {
            const float* ch = base + c * 4096;
            float v = w00 * __ldg(ch + i00) + w01 * __ldg(ch + i01)
                    + w10 * __ldg(ch + i10) + w11 * __ldg(ch + i11);
            xsplit(sbase, tid, 256 + c, v);
        }
    }
    // ---- zero pad cols 275..295 (128 rows x 21 cols) ----
    for (int idx = tid; idx < 128 * 21; idx += 512) {
        int rr = idx / 21, cc = 275 + idx % 21;
        xsplit(sbase, rr, cc, 0.f);
    }

    // fragment addresses (A from X; fixed per warp)
    u32 a_row = (u32)(r0 + (lane & 15));
    u32 a_koff = (u32)((lane >> 4) << 3);
    u32 xhi_a = sbase + SM_XHI + a_row * XSTR + a_koff * 2;
    u32 xlo_a = sbase + SM_XLO + a_row * XSTR + a_koff * 2;
    u32 b_rowsel = (u32)((lane & 7) + ((lane & 16) >> 1));
    u32 b_koff = (u32)(lane & 8);

    const float* Ws[3] = { w0, w1, w2 };
    const float* Bsx[3] = { b0, b1, b2 };

    float acc[16][4];
    for (int L = 0; L < 3; ++L) {
        const float* W = Ws[L];
#pragma unroll
        for (int i = 0; i < 16; i++)
#pragma unroll
            for (int j = 0; j < 4; j++) acc[i][j] = 0.f;
#pragma unroll 1
        for (int chunk = 0; chunk < 9; ++chunk) {
            __syncthreads();
            {   // stage W chunk: rows 256 x 32 k (pad zero beyond 274)
                int o = tid >> 1, kh = (tid & 1) * 16;
#pragma unroll 16
                for (int i = 0; i < 16; ++i) {
                    int kg = chunk * 32 + kh + i;
                    float v = (kg < 275) ? __ldg(W + o * 275 + kg) : 0.f;
                    wsplit(sbase, o, kh + i, v);
                }
            }
            __syncthreads();
#pragma unroll
            for (int ks = 0; ks < 2; ++ks) {
                int k0 = chunk * 32 + ks * 16;
                u32 ah0, ah1, ah2, ah3, al0, al1, al2, al3;
                ldsm_x4(ah0, ah1, ah2, ah3, xhi_a + k0 * 2);
                ldsm_x4(al0, al1, al2, al3, xlo_a + k0 * 2);
#pragma unroll
                for (int ng = 0; ng < 8; ++ng) {
                    int n0 = half * 128 + ng * 16;
                    u32 baddr = sbase + (n0 + b_rowsel) * WSTR + (ks * 16 + b_koff) * 2;
                    u32 bh0, bh1, bh2, bh3, bl0, bl1, bl2, bl3;
                    ldsm_x4(bh0, bh1, bh2, bh3, baddr + SM_WHI);
                    ldsm_x4(bl0, bl1, bl2, bl3, baddr + SM_WLO);
                    mma_bf16(acc[2 * ng],     ah0, ah1, ah2, ah3, bh0, bh1);
                    mma_bf16(acc[2 * ng],     ah0, ah1, ah2, ah3, bl0, bl1);
                    mma_bf16(acc[2 * ng],     al0, al1, al2, al3, bh0, bh1);
                    mma_bf16(acc[2 * ng + 1], ah0, ah1, ah2, ah3, bh2, bh3);
                    mma_bf16(acc[2 * ng + 1], ah0, ah1, ah2, ah3, bl2, bl3);
                    mma_bf16(acc[2 * ng + 1], al0, al1, al2, al3, bh2, bh3);
                }
            }
        }
        __syncthreads();   // all mma reads of X done before epilogue overwrites
        const float* bias = Bsx[L];
#pragma unroll
        for (int nt = 0; nt < 16; ++nt) {
            int colb = half * 128 + nt * 8 + (lane & 3) * 2;
            int rA = r0 + (lane >> 2);
            float bc0 = __ldg(bias + colb), bc1 = __ldg(bias + colb + 1);
            xsplit(sbase, rA, colb,         fmaxf(acc[nt][0] + bc0, 0.f));
            xsplit(sbase, rA, colb + 1,     fmaxf(acc[nt][1] + bc1, 0.f));
            xsplit(sbase, rA + 8, colb,     fmaxf(acc[nt][2] + bc0, 0.f));
            xsplit(sbase, rA + 8, colb + 1, fmaxf(acc[nt][3] + bc1, 0.f));
        }
    }

    // ---- head: 19 outs (padded to 32 rows in W buffer), half==0 warps ----
#pragma unroll
    for (int i = 0; i < 4; i++)
#pragma unroll
        for (int j = 0; j < 4; j++) acc[i][j] = 0.f;
#pragma unroll 1
    for (int chunk = 0; chunk < 9; ++chunk) {
        __syncthreads();
        if (tid < 64) {
            int o = tid >> 1, kh = (tid & 1) * 16;
#pragma unroll 16
            for (int i = 0; i < 16; ++i) {
                int kg = chunk * 32 + kh + i;
                float v = (kg < 275 && o < C_) ? __ldg(wp + o * 275 + kg) : 0.f;
                wsplit(sbase, o, kh + i, v);
            }
        }
        __syncthreads();
        if (half == 0) {
#pragma unroll
            for (int ks = 0; ks < 2; ++ks) {
                int k0 = chunk * 32 + ks * 16;
                u32 ah0, ah1, ah2, ah3, al0, al1, al2, al3;
                ldsm_x4(ah0, ah1, ah2, ah3, xhi_a + k0 * 2);
                ldsm_x4(al0, al1, al2, al3, xlo_a + k0 * 2);
#pragma unroll
                for (int ng = 0; ng < 2; ++ng) {
                    u32 baddr = sbase + (ng * 16 + b_rowsel) * WSTR + (ks * 16 + b_koff) * 2;
                    u32 bh0, bh1, bh2, bh3, bl0, bl1, bl2, bl3;
                    ldsm_x4(bh0, bh1, bh2, bh3, baddr + SM_WHI);
                    ldsm_x4(bl0, bl1, bl2, bl3, baddr + SM_WLO);
                    mma_bf16(acc[2 * ng],     ah0, ah1, ah2, ah3, bh0, bh1);
                    mma_bf16(acc[2 * ng],     ah0, ah1, ah2, ah3, bl0, bl1);
                    mma_bf16(acc[2 * ng],     al0, al1, al2, al3, bh0, bh1);
                    mma_bf16(acc[2 * ng + 1], ah0, ah1, ah2, ah3, bh2, bh3);
                    mma_bf16(acc[2 * ng + 1], ah0, ah1, ah2, ah3, bl2, bl3);
                    mma_bf16(acc[2 * ng + 1], al0, al1, al2, al3, bh2, bh3);
                }
            }
        }
    }
    if (half == 0) {
        int rA = r0 + (lane >> 2);
        int gp0 = pt0g + rA, gp1 = pt0g + rA + 8;
#pragma unroll
        for (int nt = 0; nt < 4; ++nt) {
            int colb = nt * 8 + (lane & 3) * 2;
#pragma unroll
            for (int dj = 0; dj < 2; ++dj) {
                int c = colb + dj;
                if (c < C_) {
                    float bc = __ldg(bp + c);
                    size_t rowoff = ((size_t)(nimg * C_ + c)) << 14;
                    logits[rowoff + (gp0 & 16383)] = acc[nt][dj] + bc;
                    logits[rowoff + (gp1 & 16383)] = acc[nt][2 + dj] + bc;
                }
            }
        }
    }
}

// ---------------- launch ----------------
extern "C" void kernel_launch(void* const* d_in, const int* in_sizes, int n_in,
                              void* d_out, int out_size) {
    const float* coarse = (const float*)d_in[0];
    const float* features = (const float*)d_in[1];
    const float* w0 = (const float*)d_in[2];
    const float* b0 = (const float*)d_in[3];
    const float* w1 = (const float*)d_in[4];
    const float* b1 = (const float*)d_in[5];
    const float* w2 = (const float*)d_in[6];
    const float* b2 = (const float*)d_in[7];
    const float* wp = (const float*)d_in[8];
    const float* bp = (const float*)d_in[9];
    float* out = (float*)d_out;
    float* out_coords = out + OUT_COORDS_OFF_;
    float* out_logits = out + OUT_LOGITS_OFF_;
    u64* keys = (u64*)(out + OUT_LOGITS_OFF_);   // dead until k_fused writes logits

    cudaFuncSetAttribute(k_fused, cudaFuncAttributeMaxDynamicSharedMemorySize, SMEM_TOTAL);

    cudaMemcpyAsync(out, coarse, (size_t)OUT_COARSE_ * sizeof(float),
                    cudaMemcpyDeviceToDevice, 0);

    k_gen_random<<<(N_ * RND_ * 2 + 255) / 256, 256>>>(out_coords);
    k_unc_keys<<<(N_ * SORTN_) / 256, 256>>>(coarse, keys);

    k_bitonic_local<<<256, 1024>>>(keys, 0);
    for (int k = 4096; k <= 65536; k <<= 1) {
        for (int j = k >> 1; j >= 2048; j >>= 1)
            k_bitonic_global<<<(N_ * SORTN_) / 256, 256>>>(keys, k, j);
        k_bitonic_local<<<256, 1024>>>(keys, k);
    }

    k_gather_imp<<<(N_ * IMP_ + 255) / 256, 256>>>(keys, out_coords);

    k_fused<<<ROWS_ / 128, 512, SMEM_TOTAL>>>(coarse, features, w0, b0, w1, b1,
                                              w2, b2, wp, bp, out_coords, out_logits);
}